// round 9
// baseline (speedup 1.0000x reference)
#include <cuda_runtime.h>
#include <cstddef>
#include <cstring>

#define Bv 32
#define Tv 512
#define Cv 8
#define Hv 256
#define Gv 1024

// ---------------- scratch (device globals: allocation-free) ----------------
__device__ float g_h1[(size_t)Tv * Cv * Hv * Bv];   // layer1 hidden, [T][C][H][B]
__device__ float g_hbuf[2 * Cv * Hv * Bv];          // h exchange, [2][C][H][B]
__device__ unsigned g_cnt[Cv];                      // per-channel barrier counters (zero-init)
__device__ unsigned g_sense[Cv];                    // per-channel barrier sense (zero-init)

// ---------------- math helpers ----------------
__device__ __forceinline__ float sig_(float x) {
    return __fdividef(1.0f, 1.0f + __expf(-x));
}
__device__ __forceinline__ float tanh_(float x) {
    float ax = fabsf(x);
    float e  = __expf(-2.0f * ax);
    float t  = __fdividef(1.0f - e, 1.0f + e);
    return copysignf(t, x);
}
__device__ __forceinline__ float2 u2f(unsigned long long u) {
    float2 f; memcpy(&f, &u, 8); return f;
}

// packed fp32x2 FMA (FFMA2) and operand duplication
#define FMA2(acc, h, w) asm("fma.rn.f32x2 %0, %1, %2, %0;" : "+l"(acc) : "l"(h), "l"(w))
#define PACK2(d, s)     asm("mov.b64 %0, {%1, %1};" : "=l"(d) : "f"(s))

// cp.async helpers
__device__ __forceinline__ unsigned smem_u32(const void* p) {
    unsigned r;
    asm("{ .reg .u64 t; cvta.to.shared.u64 t, %1; cvt.u32.u64 %0, t; }" : "=r"(r) : "l"(p));
    return r;
}
__device__ __forceinline__ void cp16(unsigned s, const void* g) {
    asm volatile("cp.async.cg.shared.global [%0], [%1], 16;" :: "r"(s), "l"(g));
}
#define CP_COMMIT() asm volatile("cp.async.commit_group;" ::: "memory")
#define CP_WAIT0()  asm volatile("cp.async.wait_group 0;" ::: "memory")

// per-channel sense-reversing barrier across the 16 CTAs of a channel (fallback path)
__device__ __forceinline__ void chan_barrier(int c, unsigned &lsense) {
    __syncthreads();
    if (threadIdx.x == 0) {
        __threadfence();
        unsigned a = atomicAdd(&g_cnt[c], 1u);
        if (a == 15u) {
            *(volatile unsigned*)&g_cnt[c] = 0u;
            __threadfence();
            *(volatile unsigned*)&g_sense[c] = lsense ^ 1u;
        } else {
            while (*(volatile unsigned*)&g_sense[c] == lsense) { __nanosleep(20); }
            __threadfence();
        }
    }
    lsense ^= 1u;
    __syncthreads();
}

// ---------------- smem layout (floats) ----------------
// Whh_s [256][64] : 16384 | Wih_s [256][64] : 16384 (L2)
// h_s [256][32] : 8192 | h1_s [256][32] : 8192 (L2)
// gsm/part0/part1 [32][66] : 2112 each
// c_s 512, bsum 64, wih1s 64, xs 32, wlin_s 256, ored 256
#define GSTR 66
#define SM_FLOATS (16384 + 16384 + 8192 + 8192 + 3 * 2112 + 512 + 64 + 64 + 32 + 256 + 256)
#define SM_BYTES  (SM_FLOATS * 4)

template <int LAYER, int CLUS>
__global__ __launch_bounds__(512, 1)
void lstm_kernel(const float* __restrict__ x,
                 const float* __restrict__ Wih,   // L1: [C][G][1]; L2: [C][G][H]
                 const float* __restrict__ Whh,   // [C][G][H]
                 const float* __restrict__ bih,   // [C][G]
                 const float* __restrict__ bhh,   // [C][G]
                 const float* __restrict__ Wlin,  // [C][H]  (L2)
                 const float* __restrict__ blin,  // [C]     (L2)
                 float* __restrict__ out)         // [B][T][C] (L2)
{
    extern __shared__ float sm[];
    float* Whh_s  = sm;
    float* Wih_s  = Whh_s + 16384;
    float* h_s    = Wih_s + 16384;
    float* h1_s   = h_s   + 8192;
    float* gsm    = h1_s  + 8192;
    float* part0  = gsm   + Bv * GSTR;
    float* part1  = part0 + Bv * GSTR;
    float* c_s    = part1 + Bv * GSTR;
    float* bsum   = c_s   + 512;
    float* wih1s  = bsum  + 64;
    float* xs     = wih1s + 64;
    float* wlin_s = xs    + 32;
    float* ored   = wlin_s + 256;

    const int tid   = threadIdx.x;
    const int c     = blockIdx.x >> 4;
    const int rank  = blockIdx.x & 15;
    const int jbase = rank << 4;

    // compute decomposition (R7-proven): warp = 32 row-pairs, fixed (oct, kq)
    const int rp  = tid & 31;          // row-pair -> rows 2rp, 2rp+1
    const int oct = (tid >> 5) & 3;    // batch octet -> batches oct*8..+7
    const int kq  = tid >> 7;          // k-quarter -> k in [kq*64, kq*64+64)

    // activation decomposition (coalesced global stores)
    const int ab = tid & 31;           // batch = lane
    const int aj = tid >> 5;           // local hidden idx 0..15

    // ---- init: weights k-major, biases, zero state ----
    for (int idx = tid; idx < 64 * Hv; idx += 512) {
        int k  = idx >> 6;
        int r  = idx & 63;
        int g  = r >> 4;
        int jl = r & 15;
        size_t grow = (size_t)c * Gv + g * Hv + (jbase + jl);
        Whh_s[k * 64 + r] = Whh[grow * Hv + k];
        if (LAYER == 2)
            Wih_s[k * 64 + r] = Wih[grow * Hv + k];
    }
    if (tid < 64) {
        int g = tid >> 4, jl = tid & 15;
        size_t gi = (size_t)c * Gv + g * Hv + (jbase + jl);
        bsum[tid] = bih[gi] + bhh[gi];
        if (LAYER == 1) wih1s[tid] = Wih[gi];
    }
    if (LAYER == 2 && tid < Hv) wlin_s[tid] = Wlin[c * Hv + tid];
    for (int i = tid; i < Hv * Bv; i += 512) h_s[i] = 0.0f;
    c_s[tid] = 0.0f;
    __syncthreads();

    const float blin_c = (LAYER == 2) ? __ldg(&blin[c]) : 0.0f;
    const unsigned h1s_addr = smem_u32(h1_s) + (unsigned)tid * 16u;

    // ---- prefetch step-0 inputs ----
    float xr = 0.0f;
    if (LAYER == 2) {
        const float* src = g_h1 + ((size_t)0 * Cv + c) * (Hv * Bv) + tid * 4;
        #pragma unroll
        for (int i = 0; i < 4; ++i) cp16(h1s_addr + i * 512u * 16u, src + i * 512 * 4);
        CP_COMMIT();
    } else {
        if (tid < Bv) xr = __ldg(&x[(size_t)tid * Tv * Cv + c]);
    }

    unsigned lsense = 0;

    for (int t = 0; t < Tv; ++t) {
        // ---- inputs ready ----
        if (LAYER == 2) {
            CP_WAIT0();
        } else {
            if (tid < Bv) xs[tid] = xr;
        }
        __syncthreads();   // h_s reload (prev step) + staged inputs visible

        // ---- gate mat-vecs: rows {2rp,2rp+1} x batches oct*8..+7 over k-quarter ----
        unsigned long long A[8], Bk[8];
        #pragma unroll
        for (int i = 0; i < 8; ++i) { A[i] = 0ull; Bk[i] = 0ull; }
        {
            const float* wh  = Whh_s + kq * 64 * 64 + 2 * rp;
            const float* hpp = h_s   + kq * 64 * 32 + oct * 8;
            const float* wi  = Wih_s + kq * 64 * 64 + 2 * rp;
            const float* ppp = h1_s  + kq * 64 * 32 + oct * 8;

            #pragma unroll 4
            for (int kk = 0; kk < 64; ++kk) {
                float2 wv = *(const float2*)wh;  wh += 64;
                unsigned long long w0, w1;
                PACK2(w0, wv.x); PACK2(w1, wv.y);
                ulonglong2 ha = *(const ulonglong2*)hpp;
                ulonglong2 hb = *(const ulonglong2*)(hpp + 4);  hpp += 32;
                FMA2(A[0], ha.x, w0); FMA2(A[1], ha.y, w0);
                FMA2(A[2], hb.x, w0); FMA2(A[3], hb.y, w0);
                FMA2(A[4], ha.x, w1); FMA2(A[5], ha.y, w1);
                FMA2(A[6], hb.x, w1); FMA2(A[7], hb.y, w1);

                if (LAYER == 2) {
                    float2 vv = *(const float2*)wi;  wi += 64;
                    unsigned long long v0, v1;
                    PACK2(v0, vv.x); PACK2(v1, vv.y);
                    ulonglong2 pa = *(const ulonglong2*)ppp;
                    ulonglong2 pb = *(const ulonglong2*)(ppp + 4);  ppp += 32;
                    FMA2(Bk[0], pa.x, v0); FMA2(Bk[1], pa.y, v0);
                    FMA2(Bk[2], pb.x, v0); FMA2(Bk[3], pb.y, v0);
                    FMA2(Bk[4], pa.x, v1); FMA2(Bk[5], pa.y, v1);
                    FMA2(Bk[6], pb.x, v1); FMA2(Bk[7], pb.y, v1);
                }
            }
        }
        // merge hh + ih accumulators
        float2 R[8];
        #pragma unroll
        for (int i = 0; i < 8; ++i) {
            float2 fa = u2f(A[i]);
            if (LAYER == 2) { float2 fb = u2f(Bk[i]); fa.x += fb.x; fa.y += fb.y; }
            R[i] = fa;
        }

        // ---- cross-kq reduction: kq 0->gsm, 2->part0, 3->part1; kq1 combines ----
        {
            float* dst = (kq == 0) ? gsm : (kq == 2) ? part0 : (kq == 3) ? part1 : (float*)0;
            if (dst) {
                #pragma unroll
                for (int p = 0; p < 4; ++p) {
                    int b = oct * 8 + 2 * p;
                    *(float2*)(dst + b * GSTR + 2 * rp)       = make_float2(R[p].x, R[4 + p].x);
                    *(float2*)(dst + (b + 1) * GSTR + 2 * rp) = make_float2(R[p].y, R[4 + p].y);
                }
            }
        }
        __syncthreads();   // sync1: h1_s reads done, kq0/kq2/kq3 partials written

        // ---- prefetch next step's inputs (h1_s dead until next loop top) ----
        if (LAYER == 2) {
            if (t + 1 < Tv) {
                const float* src = g_h1 + ((size_t)(t + 1) * Cv + c) * (Hv * Bv) + tid * 4;
                #pragma unroll
                for (int i = 0; i < 4; ++i) cp16(h1s_addr + i * 512u * 16u, src + i * 512 * 4);
                CP_COMMIT();
            }
        } else {
            if (tid < Bv && t + 1 < Tv)
                xr = __ldg(&x[(size_t)tid * Tv * Cv + (t + 1) * Cv + c]);
        }

        if (kq == 1) {
            #pragma unroll
            for (int p = 0; p < 4; ++p) {
                int b = oct * 8 + 2 * p;
                float2* g0 = (float2*)(gsm + b * GSTR + 2 * rp);
                float2* g1 = (float2*)(gsm + (b + 1) * GSTR + 2 * rp);
                float2 p00 = *(float2*)(part0 + b * GSTR + 2 * rp);
                float2 p01 = *(float2*)(part0 + (b + 1) * GSTR + 2 * rp);
                float2 p10 = *(float2*)(part1 + b * GSTR + 2 * rp);
                float2 p11 = *(float2*)(part1 + (b + 1) * GSTR + 2 * rp);
                float2 a = *g0, bb = *g1;
                a.x  += p00.x + p10.x + R[p].x;
                a.y  += p00.y + p10.y + R[4 + p].x;
                bb.x += p01.x + p11.x + R[p].y;
                bb.y += p01.y + p11.y + R[4 + p].y;
                *g0 = a; *g1 = bb;
            }
        }
        __syncthreads();   // sync2: gsm final

        // ---- activations + state update: thread -> (b = lane, j = warp) ----
        {
            const float* gr = gsm + ab * GSTR;
            float vi = gr[      aj] + bsum[      aj];
            float vf = gr[16 + aj] + bsum[16 + aj];
            float vg = gr[32 + aj] + bsum[32 + aj];
            float vo = gr[48 + aj] + bsum[48 + aj];
            if (LAYER == 1) {
                float xv = xs[ab];
                vi = fmaf(xv, wih1s[     aj], vi);
                vf = fmaf(xv, wih1s[16 + aj], vf);
                vg = fmaf(xv, wih1s[32 + aj], vg);
                vo = fmaf(xv, wih1s[48 + aj], vo);
            }
            float iv = sig_(vi), fv = sig_(vf), gv = tanh_(vg), ov = sig_(vo);
            float cn = fmaf(fv, c_s[tid], iv * gv);
            c_s[tid] = cn;
            float hn = ov * tanh_(cn);
            size_t hoff = ((size_t)c * Hv + jbase + aj) * Bv + ab;   // coalesced
            g_hbuf[(size_t)(t & 1) * (Cv * Hv * Bv) + hoff] = hn;
            if (LAYER == 1)
                g_h1[(((size_t)t * Cv + c) * Hv + jbase + aj) * Bv + ab] = hn;
        }

        // ---- channel barrier: HW cluster barrier, or atomic fallback ----
        if (CLUS) {
            // arrive: release (covers the hn global stores); wait: acquire.
            asm volatile("barrier.cluster.arrive.aligned;" ::: "memory");
            asm volatile("barrier.cluster.wait.aligned;" ::: "memory");
        } else {
            chan_barrier(c, lsense);
        }

        // ---- reload full h[t] for this channel into h_s[k][b] ----
        {
            const float4* src = (const float4*)(g_hbuf + (size_t)(t & 1) * (Cv * Hv * Bv)
                                                        + (size_t)c * Hv * Bv);
            float4* dst = (float4*)h_s;
            #pragma unroll
            for (int i = 0; i < 4; ++i)
                dst[tid + i * 512] = __ldcg(src + tid + i * 512);
        }

        // ---- final linear head (layer2, rank-0 CTA) ----
        if (LAYER == 2 && rank == 0) {
            __syncthreads();     // h_s reload visible
            if (tid < 256) {
                int w = tid >> 5, b = tid & 31;
                const float* hp = h_s + w * 32 * 32 + b;
                const float* wl = wlin_s + w * 32;
                float s = 0.0f;
                #pragma unroll
                for (int k2 = 0; k2 < 32; ++k2)
                    s = fmaf(hp[k2 * 32], wl[k2], s);
                ored[w * 32 + b] = s;
            }
            __syncthreads();
            if (tid < 32) {
                float s = blin_c;
                #pragma unroll
                for (int w = 0; w < 8; ++w) s += ored[w * 32 + tid];
                out[(size_t)tid * Tv * Cv + t * Cv + c] = s;
            }
        }
        // loop-top __syncthreads orders h_s reload before next compute
    }
}

// ---------------- launch ----------------
template <int LAYER>
static void launch_layer(const float* x, const float* Wih, const float* Whh,
                         const float* bih, const float* bhh,
                         const float* Wlin, const float* blin, float* out)
{
    static bool inited = false;
    if (!inited) {
        cudaFuncSetAttribute(lstm_kernel<LAYER, 1>, cudaFuncAttributeMaxDynamicSharedMemorySize, SM_BYTES);
        cudaFuncSetAttribute(lstm_kernel<LAYER, 1>, cudaFuncAttributeNonPortableClusterSizeAllowed, 1);
        cudaFuncSetAttribute(lstm_kernel<LAYER, 0>, cudaFuncAttributeMaxDynamicSharedMemorySize, SM_BYTES);
        inited = true;
    }

    cudaLaunchConfig_t cfg = {};
    cfg.gridDim  = dim3(128, 1, 1);
    cfg.blockDim = dim3(512, 1, 1);
    cfg.dynamicSmemBytes = SM_BYTES;
    cfg.stream = 0;
    cudaLaunchAttribute attrs[1];
    attrs[0].id = cudaLaunchAttributeClusterDimension;
    attrs[0].val.clusterDim.x = 16;
    attrs[0].val.clusterDim.y = 1;
    attrs[0].val.clusterDim.z = 1;
    cfg.attrs = attrs;
    cfg.numAttrs = 1;

    cudaError_t err = cudaLaunchKernelEx(&cfg, lstm_kernel<LAYER, 1>,
                                         x, Wih, Whh, bih, bhh, Wlin, blin, out);
    if (err != cudaSuccess) {
        (void)cudaGetLastError();   // clear error state; use atomic-barrier fallback
        lstm_kernel<LAYER, 0><<<128, 512, SM_BYTES>>>(x, Wih, Whh, bih, bhh, Wlin, blin, out);
    }
}

extern "C" void kernel_launch(void* const* d_in, const int* in_sizes, int n_in,
                              void* d_out, int out_size)
{
    const float* x    = (const float*)d_in[0];
    const float* Wih1 = (const float*)d_in[1];
    const float* Whh1 = (const float*)d_in[2];
    const float* bih1 = (const float*)d_in[3];
    const float* bhh1 = (const float*)d_in[4];
    const float* Wih2 = (const float*)d_in[5];
    const float* Whh2 = (const float*)d_in[6];
    const float* bih2 = (const float*)d_in[7];
    const float* bhh2 = (const float*)d_in[8];
    const float* Wlin = (const float*)d_in[9];
    const float* blin = (const float*)d_in[10];
    float* out = (float*)d_out;

    (void)in_sizes; (void)n_in; (void)out_size;

    launch_layer<1>(x, Wih1, Whh1, bih1, bhh1, nullptr, nullptr, nullptr);
    launch_layer<2>(nullptr, Wih2, Whh2, bih2, bhh2, Wlin, blin, out);
}

// round 10
// speedup vs baseline: 1.6602x; 1.6602x over previous
#include <cuda_runtime.h>
#include <cstddef>
#include <cstring>

#define Bv 32
#define Tv 512
#define Cv 8
#define Hv 256
#define Gv 1024

// ---------------- scratch (device globals: allocation-free) ----------------
__device__ float g_h1[(size_t)Tv * Cv * Hv * Bv];   // layer1 hidden, [T][C][H][B]
__device__ float g_h2[(size_t)Tv * Cv * Hv * Bv];   // layer2 hidden, [T][C][H][B]
__device__ float g_hbuf[2 * Cv * Hv * Bv];          // h exchange, [2][C][H][B]
__device__ unsigned g_cnt[Cv];                      // per-channel barrier counters (zero-init)
__device__ unsigned g_sense[Cv];                    // per-channel barrier sense (zero-init)

// ---------------- math helpers ----------------
__device__ __forceinline__ float sig_(float x) {
    return __fdividef(1.0f, 1.0f + __expf(-x));
}
__device__ __forceinline__ float tanh_(float x) {
    float ax = fabsf(x);
    float e  = __expf(-2.0f * ax);
    float t  = __fdividef(1.0f - e, 1.0f + e);
    return copysignf(t, x);
}
__device__ __forceinline__ float2 u2f(unsigned long long u) {
    float2 f; memcpy(&f, &u, 8); return f;
}

// packed fp32x2 FMA (FFMA2) and operand duplication
#define FMA2(acc, h, w) asm("fma.rn.f32x2 %0, %1, %2, %0;" : "+l"(acc) : "l"(h), "l"(w))
#define PACK2(d, s)     asm("mov.b64 %0, {%1, %1};" : "=l"(d) : "f"(s))

// cp.async helpers
__device__ __forceinline__ unsigned smem_u32(const void* p) {
    unsigned r;
    asm("{ .reg .u64 t; cvta.to.shared.u64 t, %1; cvt.u32.u64 %0, t; }" : "=r"(r) : "l"(p));
    return r;
}
__device__ __forceinline__ void cp16(unsigned s, const void* g) {
    asm volatile("cp.async.cg.shared.global [%0], [%1], 16;" :: "r"(s), "l"(g));
}
#define CP_COMMIT() asm volatile("cp.async.commit_group;" ::: "memory")
#define CP_WAIT0()  asm volatile("cp.async.wait_group 0;" ::: "memory")

// per-channel sense-reversing barrier across the 16 CTAs of a channel (R4/R7-proven)
__device__ __forceinline__ void chan_barrier(int c, unsigned &lsense) {
    __syncthreads();
    if (threadIdx.x == 0) {
        __threadfence();
        unsigned a = atomicAdd(&g_cnt[c], 1u);
        if (a == 15u) {
            *(volatile unsigned*)&g_cnt[c] = 0u;
            __threadfence();
            *(volatile unsigned*)&g_sense[c] = lsense ^ 1u;
        } else {
            while (*(volatile unsigned*)&g_sense[c] == lsense) { __nanosleep(20); }
            __threadfence();
        }
    }
    lsense ^= 1u;
    __syncthreads();
}

// ---------------- smem layout (floats) ----------------
// WW_s : 32768   L1: Whh [256][64]; L2: interleaved [256][32 rowpairs][whh0,whh1,wih0,wih1]
// h_s [256][32] : 8192 | h1_s [256][32] : 8192 (L2 staging)
// gsm/part0/part1 [32][66] : 2112 each
// c_s 512, bsum 64, wih1s 64, xs 32
#define GSTR 66
#define SM_FLOATS (32768 + 8192 + 8192 + 3 * 2112 + 512 + 64 + 64 + 32)
#define SM_BYTES  (SM_FLOATS * 4)   // 224,640 B

template <int LAYER>
__global__ __launch_bounds__(512, 1)
void lstm_kernel(const float* __restrict__ x,
                 const float* __restrict__ Wih,   // L1: [C][G][1]; L2: [C][G][H]
                 const float* __restrict__ Whh,   // [C][G][H]
                 const float* __restrict__ bih,   // [C][G]
                 const float* __restrict__ bhh)   // [C][G]
{
    extern __shared__ float sm[];
    float* WW_s   = sm;
    float* h_s    = WW_s + 32768;
    float* h1_s   = h_s   + 8192;
    float* gsm    = h1_s  + 8192;
    float* part0  = gsm   + Bv * GSTR;
    float* part1  = part0 + Bv * GSTR;
    float* c_s    = part1 + Bv * GSTR;
    float* bsum   = c_s   + 512;
    float* wih1s  = bsum  + 64;
    float* xs     = wih1s + 64;

    const int tid   = threadIdx.x;
    const int c     = blockIdx.x >> 4;
    const int rank  = blockIdx.x & 15;
    const int jbase = rank << 4;

    // compute decomposition (R7-proven): warp = 32 row-pairs, fixed (oct, kq)
    const int rp  = tid & 31;          // row-pair -> rows 2rp, 2rp+1
    const int oct = (tid >> 5) & 3;    // batch octet -> batches oct*8..+7
    const int kq  = tid >> 7;          // k-quarter -> k in [kq*64, kq*64+64)

    // activation decomposition (coalesced global stores)
    const int ab = tid & 31;           // batch = lane
    const int aj = tid >> 5;           // local hidden idx 0..15

    // ---- init: weights k-major (L2: whh/wih interleaved), biases, zero state ----
    for (int idx = tid; idx < 64 * Hv; idx += 512) {
        int k  = idx >> 6;
        int r  = idx & 63;
        int g  = r >> 4;
        int jl = r & 15;
        size_t grow = (size_t)c * Gv + g * Hv + (jbase + jl);
        if (LAYER == 2) {
            int rpp = r >> 1, par = r & 1;
            WW_s[k * 128 + rpp * 4 + par]     = Whh[grow * Hv + k];
            WW_s[k * 128 + rpp * 4 + 2 + par] = Wih[grow * Hv + k];
        } else {
            WW_s[k * 64 + r] = Whh[grow * Hv + k];
        }
    }
    if (tid < 64) {
        int g = tid >> 4, jl = tid & 15;
        size_t gi = (size_t)c * Gv + g * Hv + (jbase + jl);
        bsum[tid] = bih[gi] + bhh[gi];
        if (LAYER == 1) wih1s[tid] = Wih[gi];
    }
    for (int i = tid; i < Hv * Bv; i += 512) h_s[i] = 0.0f;
    c_s[tid] = 0.0f;
    __syncthreads();

    const unsigned h1s_addr = smem_u32(h1_s) + (unsigned)tid * 16u;

    // ---- prefetch step-0 inputs ----
    float xr = 0.0f;
    if (LAYER == 2) {
        const float* src = g_h1 + ((size_t)0 * Cv + c) * (Hv * Bv) + tid * 4;
        #pragma unroll
        for (int i = 0; i < 4; ++i) cp16(h1s_addr + i * 512u * 16u, src + i * 512 * 4);
        CP_COMMIT();
    } else {
        if (tid < Bv) xr = __ldg(&x[(size_t)tid * Tv * Cv + c]);
    }

    unsigned lsense = 0;

    for (int t = 0; t < Tv; ++t) {
        // ---- inputs ready ----
        if (LAYER == 2) {
            CP_WAIT0();
        } else {
            if (tid < Bv) xs[tid] = xr;
        }
        __syncthreads();   // h_s reload (prev step) + staged inputs visible

        // ---- gate mat-vecs: rows {2rp,2rp+1} x batches oct*8..+7 over k-quarter ----
        unsigned long long A[8], Bk[8];
        #pragma unroll
        for (int i = 0; i < 8; ++i) { A[i] = 0ull; Bk[i] = 0ull; }
        if (LAYER == 2) {
            const float* ww  = WW_s + kq * 64 * 128 + 4 * rp;
            const float* hpp = h_s  + kq * 64 * 32 + oct * 8;
            const float* ppp = h1_s + kq * 64 * 32 + oct * 8;

            #pragma unroll 4
            for (int kk = 0; kk < 64; ++kk) {
                float4 wv = *(const float4*)ww;  ww += 128;
                unsigned long long w0, w1, v0, v1;
                PACK2(w0, wv.x); PACK2(w1, wv.y);
                PACK2(v0, wv.z); PACK2(v1, wv.w);
                ulonglong2 ha = *(const ulonglong2*)hpp;
                ulonglong2 hb = *(const ulonglong2*)(hpp + 4);  hpp += 32;
                FMA2(A[0], ha.x, w0); FMA2(A[1], ha.y, w0);
                FMA2(A[2], hb.x, w0); FMA2(A[3], hb.y, w0);
                FMA2(A[4], ha.x, w1); FMA2(A[5], ha.y, w1);
                FMA2(A[6], hb.x, w1); FMA2(A[7], hb.y, w1);

                ulonglong2 pa = *(const ulonglong2*)ppp;
                ulonglong2 pb = *(const ulonglong2*)(ppp + 4);  ppp += 32;
                FMA2(Bk[0], pa.x, v0); FMA2(Bk[1], pa.y, v0);
                FMA2(Bk[2], pb.x, v0); FMA2(Bk[3], pb.y, v0);
                FMA2(Bk[4], pa.x, v1); FMA2(Bk[5], pa.y, v1);
                FMA2(Bk[6], pb.x, v1); FMA2(Bk[7], pb.y, v1);
            }
        } else {
            const float* wh  = WW_s + kq * 64 * 64 + 2 * rp;
            const float* hpp = h_s  + kq * 64 * 32 + oct * 8;

            #pragma unroll 4
            for (int kk = 0; kk < 64; ++kk) {
                float2 wv = *(const float2*)wh;  wh += 64;
                unsigned long long w0, w1;
                PACK2(w0, wv.x); PACK2(w1, wv.y);
                ulonglong2 ha = *(const ulonglong2*)hpp;
                ulonglong2 hb = *(const ulonglong2*)(hpp + 4);  hpp += 32;
                FMA2(A[0], ha.x, w0); FMA2(A[1], ha.y, w0);
                FMA2(A[2], hb.x, w0); FMA2(A[3], hb.y, w0);
                FMA2(A[4], ha.x, w1); FMA2(A[5], ha.y, w1);
                FMA2(A[6], hb.x, w1); FMA2(A[7], hb.y, w1);
            }
        }
        // merge hh + ih accumulators
        float2 R[8];
        #pragma unroll
        for (int i = 0; i < 8; ++i) {
            float2 fa = u2f(A[i]);
            if (LAYER == 2) { float2 fb = u2f(Bk[i]); fa.x += fb.x; fa.y += fb.y; }
            R[i] = fa;
        }

        // ---- cross-kq reduction: kq 0->gsm, 2->part0, 3->part1; kq1 combines ----
        {
            float* dst = (kq == 0) ? gsm : (kq == 2) ? part0 : (kq == 3) ? part1 : (float*)0;
            if (dst) {
                #pragma unroll
                for (int p = 0; p < 4; ++p) {
                    int b = oct * 8 + 2 * p;
                    *(float2*)(dst + b * GSTR + 2 * rp)       = make_float2(R[p].x, R[4 + p].x);
                    *(float2*)(dst + (b + 1) * GSTR + 2 * rp) = make_float2(R[p].y, R[4 + p].y);
                }
            }
        }
        __syncthreads();   // sync1: h1_s reads done, kq0/kq2/kq3 partials written

        // ---- prefetch next step's inputs (h1_s dead until next loop top) ----
        if (LAYER == 2) {
            if (t + 1 < Tv) {
                const float* src = g_h1 + ((size_t)(t + 1) * Cv + c) * (Hv * Bv) + tid * 4;
                #pragma unroll
                for (int i = 0; i < 4; ++i) cp16(h1s_addr + i * 512u * 16u, src + i * 512 * 4);
                CP_COMMIT();
            }
        } else {
            if (tid < Bv && t + 1 < Tv)
                xr = __ldg(&x[(size_t)tid * Tv * Cv + (t + 1) * Cv + c]);
        }

        if (kq == 1) {
            #pragma unroll
            for (int p = 0; p < 4; ++p) {
                int b = oct * 8 + 2 * p;
                float2* g0 = (float2*)(gsm + b * GSTR + 2 * rp);
                float2* g1 = (float2*)(gsm + (b + 1) * GSTR + 2 * rp);
                float2 p00 = *(float2*)(part0 + b * GSTR + 2 * rp);
                float2 p01 = *(float2*)(part0 + (b + 1) * GSTR + 2 * rp);
                float2 p10 = *(float2*)(part1 + b * GSTR + 2 * rp);
                float2 p11 = *(float2*)(part1 + (b + 1) * GSTR + 2 * rp);
                float2 a = *g0, bb = *g1;
                a.x  += p00.x + p10.x + R[p].x;
                a.y  += p00.y + p10.y + R[4 + p].x;
                bb.x += p01.x + p11.x + R[p].y;
                bb.y += p01.y + p11.y + R[4 + p].y;
                *g0 = a; *g1 = bb;
            }
        }
        __syncthreads();   // sync2: gsm final

        // ---- activations + state update: thread -> (b = lane, j = warp) ----
        {
            const float* gr = gsm + ab * GSTR;
            float vi = gr[      aj] + bsum[      aj];
            float vf = gr[16 + aj] + bsum[16 + aj];
            float vg = gr[32 + aj] + bsum[32 + aj];
            float vo = gr[48 + aj] + bsum[48 + aj];
            if (LAYER == 1) {
                float xv = xs[ab];
                vi = fmaf(xv, wih1s[     aj], vi);
                vf = fmaf(xv, wih1s[16 + aj], vf);
                vg = fmaf(xv, wih1s[32 + aj], vg);
                vo = fmaf(xv, wih1s[48 + aj], vo);
            }
            float iv = sig_(vi), fv = sig_(vf), gv = tanh_(vg), ov = sig_(vo);
            float cn = fmaf(fv, c_s[tid], iv * gv);
            c_s[tid] = cn;
            float hn = ov * tanh_(cn);
            size_t hoff = ((size_t)c * Hv + jbase + aj) * Bv + ab;   // coalesced
            g_hbuf[(size_t)(t & 1) * (Cv * Hv * Bv) + hoff] = hn;
            size_t hist = (((size_t)t * Cv + c) * Hv + jbase + aj) * Bv + ab;
            if (LAYER == 1) g_h1[hist] = hn;
            else            g_h2[hist] = hn;
        }

        chan_barrier(c, lsense);

        // ---- reload full h[t] for this channel into h_s[k][b] ----
        {
            const float4* src = (const float4*)(g_hbuf + (size_t)(t & 1) * (Cv * Hv * Bv)
                                                        + (size_t)c * Hv * Bv);
            float4* dst = (float4*)h_s;
            #pragma unroll
            for (int i = 0; i < 4; ++i)
                dst[tid + i * 512] = __ldcg(src + tid + i * 512);
        }
        // loop-top __syncthreads orders h_s reload before next compute
    }
}

// ---------------- post head: out[b][t][c] = sum_k h2[t][c][k][b]*Wlin[c][k] + blin[c] ----------------
__global__ __launch_bounds__(256)
void head_kernel(const float* __restrict__ Wlin,
                 const float* __restrict__ blin,
                 float* __restrict__ out)
{
    __shared__ float wls[256];
    __shared__ float red[256];
    const int blk = blockIdx.x;          // t*Cv + c
    const int c   = blk & (Cv - 1);
    const int t   = blk >> 3;
    const int w   = threadIdx.x >> 5;
    const int b   = threadIdx.x & 31;

    wls[threadIdx.x] = __ldg(&Wlin[c * Hv + threadIdx.x]);
    __syncthreads();

    const float* hp = g_h2 + ((size_t)blk * Hv + w * 32) * Bv + b;
    const float* wl = wls + w * 32;
    float s = 0.0f;
    #pragma unroll
    for (int k2 = 0; k2 < 32; ++k2)
        s = fmaf(hp[(size_t)k2 * Bv], wl[k2], s);
    red[w * 32 + b] = s;
    __syncthreads();

    if (threadIdx.x < 32) {
        float s2 = __ldg(&blin[c]);
        #pragma unroll
        for (int q = 0; q < 8; ++q) s2 += red[q * 32 + threadIdx.x];
        out[(size_t)threadIdx.x * Tv * Cv + t * Cv + c] = s2;
    }
}

// ---------------- launch ----------------
extern "C" void kernel_launch(void* const* d_in, const int* in_sizes, int n_in,
                              void* d_out, int out_size)
{
    const float* x    = (const float*)d_in[0];
    const float* Wih1 = (const float*)d_in[1];
    const float* Whh1 = (const float*)d_in[2];
    const float* bih1 = (const float*)d_in[3];
    const float* bhh1 = (const float*)d_in[4];
    const float* Wih2 = (const float*)d_in[5];
    const float* Whh2 = (const float*)d_in[6];
    const float* bih2 = (const float*)d_in[7];
    const float* bhh2 = (const float*)d_in[8];
    const float* Wlin = (const float*)d_in[9];
    const float* blin = (const float*)d_in[10];
    float* out = (float*)d_out;

    (void)in_sizes; (void)n_in; (void)out_size;

    cudaFuncSetAttribute(lstm_kernel<1>, cudaFuncAttributeMaxDynamicSharedMemorySize, SM_BYTES);
    cudaFuncSetAttribute(lstm_kernel<2>, cudaFuncAttributeMaxDynamicSharedMemorySize, SM_BYTES);

    lstm_kernel<1><<<128, 512, SM_BYTES>>>(x, Wih1, Whh1, bih1, bhh1);
    lstm_kernel<2><<<128, 512, SM_BYTES>>>(nullptr, Wih2, Whh2, bih2, bhh2);
    head_kernel<<<Tv * Cv, 256>>>(Wlin, blin, out);
}

// round 13
// speedup vs baseline: 1.7270x; 1.0402x over previous
#include <cuda_runtime.h>
#include <cstddef>
#include <cstring>

#define Bv 32
#define Tv 512
#define Cv 8
#define Hv 256
#define Gv 1024

// ---------------- scratch (device globals: allocation-free) ----------------
__device__ float g_h1[(size_t)Tv * Cv * Hv * Bv];   // layer1 hidden, [T][C][H][B]
__device__ float g_hbuf[2 * Cv * Hv * Bv];          // h exchange, [2][C][H][B]
__device__ float g_opart[(size_t)Tv * Cv * 16 * Bv]; // per-rank head partials [T][C][rank][B]
__device__ unsigned g_cnt[Cv];                      // per-channel barrier counters (zero-init)
__device__ unsigned g_sense[Cv];                    // per-channel barrier sense (zero-init)

// ---------------- math helpers ----------------
__device__ __forceinline__ float sig_(float x) {
    return __fdividef(1.0f, 1.0f + __expf(-x));
}
__device__ __forceinline__ float tanh_(float x) {
    float ax = fabsf(x);
    float e  = __expf(-2.0f * ax);
    float t  = __fdividef(1.0f - e, 1.0f + e);
    return copysignf(t, x);
}
__device__ __forceinline__ float2 u2f(unsigned long long u) {
    float2 f; memcpy(&f, &u, 8); return f;
}

// packed fp32x2 FMA (FFMA2) and operand duplication
#define FMA2(acc, h, w) asm("fma.rn.f32x2 %0, %1, %2, %0;" : "+l"(acc) : "l"(h), "l"(w))
#define PACK2(d, s)     asm("mov.b64 %0, {%1, %1};" : "=l"(d) : "f"(s))

// cp.async helpers
__device__ __forceinline__ unsigned smem_u32(const void* p) {
    unsigned r;
    asm("{ .reg .u64 t; cvta.to.shared.u64 t, %1; cvt.u32.u64 %0, t; }" : "=r"(r) : "l"(p));
    return r;
}
__device__ __forceinline__ void cp16(unsigned s, const void* g) {
    asm volatile("cp.async.cg.shared.global [%0], [%1], 16;" :: "r"(s), "l"(g));
}
#define CP_COMMIT() asm volatile("cp.async.commit_group;" ::: "memory")
#define CP_WAIT0()  asm volatile("cp.async.wait_group 0;" ::: "memory")

// per-channel sense-reversing barrier across the 16 CTAs of a channel (R4/R7-proven, BYTE-IDENTICAL)
__device__ __forceinline__ void chan_barrier(int c, unsigned &lsense) {
    __syncthreads();
    if (threadIdx.x == 0) {
        __threadfence();
        unsigned a = atomicAdd(&g_cnt[c], 1u);
        if (a == 15u) {
            *(volatile unsigned*)&g_cnt[c] = 0u;
            __threadfence();
            *(volatile unsigned*)&g_sense[c] = lsense ^ 1u;
        } else {
            while (*(volatile unsigned*)&g_sense[c] == lsense) { __nanosleep(20); }
            __threadfence();
        }
    }
    lsense ^= 1u;
    __syncthreads();
}

// ---------------- smem layout (floats) ----------------
// Whh_s [256][64] : 16384 | Wih_s [256][64] : 16384 (L2)
// h_s [256][32] : 8192 | h1_s [256][32] : 8192 (L2)
// gsm/part0/part1 [32][66] : 2112 each   (part0 doubles as head staging after sync2)
// c_s 512, bsum 64, wih1s 64, xs 32, wlin16 16
#define GSTR 66
#define SM_FLOATS (16384 + 16384 + 8192 + 8192 + 3 * 2112 + 512 + 64 + 64 + 32 + 16)
#define SM_BYTES  (SM_FLOATS * 4)

template <int LAYER>
__global__ __launch_bounds__(512, 1)
void lstm_kernel(const float* __restrict__ x,
                 const float* __restrict__ Wih,   // L1: [C][G][1]; L2: [C][G][H]
                 const float* __restrict__ Whh,   // [C][G][H]
                 const float* __restrict__ bih,   // [C][G]
                 const float* __restrict__ bhh,   // [C][G]
                 const float* __restrict__ Wlin)  // [C][H]  (L2)
{
    extern __shared__ float sm[];
    float* Whh_s  = sm;
    float* Wih_s  = Whh_s + 16384;
    float* h_s    = Wih_s + 16384;
    float* h1_s   = h_s   + 8192;
    float* gsm    = h1_s  + 8192;
    float* part0  = gsm   + Bv * GSTR;
    float* part1  = part0 + Bv * GSTR;
    float* c_s    = part1 + Bv * GSTR;
    float* bsum   = c_s   + 512;
    float* wih1s  = bsum  + 64;
    float* xs     = wih1s + 64;
    float* wlin16 = xs    + 32;

    const int tid   = threadIdx.x;
    const int c     = blockIdx.x >> 4;
    const int rank  = blockIdx.x & 15;
    const int jbase = rank << 4;

    // compute decomposition (R7-proven): warp = 32 row-pairs, fixed (oct, kq)
    const int rp  = tid & 31;          // row-pair -> rows 2rp, 2rp+1
    const int oct = (tid >> 5) & 3;    // batch octet -> batches oct*8..+7
    const int kq  = tid >> 7;          // k-quarter -> k in [kq*64, kq*64+64)

    // activation decomposition (coalesced global stores)
    const int ab = tid & 31;           // batch = lane
    const int aj = tid >> 5;           // local hidden idx 0..15

    // ---- init: weights k-major, biases, zero state ----
    for (int idx = tid; idx < 64 * Hv; idx += 512) {
        int k  = idx >> 6;
        int r  = idx & 63;
        int g  = r >> 4;
        int jl = r & 15;
        size_t grow = (size_t)c * Gv + g * Hv + (jbase + jl);
        Whh_s[k * 64 + r] = Whh[grow * Hv + k];
        if (LAYER == 2)
            Wih_s[k * 64 + r] = Wih[grow * Hv + k];
    }
    if (tid < 64) {
        int g = tid >> 4, jl = tid & 15;
        size_t gi = (size_t)c * Gv + g * Hv + (jbase + jl);
        bsum[tid] = bih[gi] + bhh[gi];
        if (LAYER == 1) wih1s[tid] = Wih[gi];
    }
    if (LAYER == 2 && tid < 16) wlin16[tid] = Wlin[c * Hv + jbase + tid];  // this CTA's slice
    for (int i = tid; i < Hv * Bv; i += 512) h_s[i] = 0.0f;
    c_s[tid] = 0.0f;
    __syncthreads();

    const unsigned h1s_addr = smem_u32(h1_s) + (unsigned)tid * 16u;

    // ---- prefetch step-0 inputs ----
    float xr = 0.0f;
    if (LAYER == 2) {
        const float* src = g_h1 + ((size_t)0 * Cv + c) * (Hv * Bv) + tid * 4;
        #pragma unroll
        for (int i = 0; i < 4; ++i) cp16(h1s_addr + i * 512u * 16u, src + i * 512 * 4);
        CP_COMMIT();
    } else {
        if (tid < Bv) xr = __ldg(&x[(size_t)tid * Tv * Cv + c]);
    }

    unsigned lsense = 0;

    for (int t = 0; t < Tv; ++t) {
        // ---- inputs ready ----
        if (LAYER == 2) {
            CP_WAIT0();
        } else {
            if (tid < Bv) xs[tid] = xr;
        }
        __syncthreads();   // h_s reload (prev step) + staged inputs visible

        // ---- gate mat-vecs: rows {2rp,2rp+1} x batches oct*8..+7 over k-quarter ----
        unsigned long long A[8], Bk[8];
        #pragma unroll
        for (int i = 0; i < 8; ++i) { A[i] = 0ull; Bk[i] = 0ull; }
        {
            const float* wh  = Whh_s + kq * 64 * 64 + 2 * rp;
            const float* hpp = h_s   + kq * 64 * 32 + oct * 8;
            const float* wi  = Wih_s + kq * 64 * 64 + 2 * rp;
            const float* ppp = h1_s  + kq * 64 * 32 + oct * 8;

            #pragma unroll 4
            for (int kk = 0; kk < 64; ++kk) {
                float2 wv = *(const float2*)wh;  wh += 64;
                unsigned long long w0, w1;
                PACK2(w0, wv.x); PACK2(w1, wv.y);
                ulonglong2 ha = *(const ulonglong2*)hpp;
                ulonglong2 hb = *(const ulonglong2*)(hpp + 4);  hpp += 32;
                FMA2(A[0], ha.x, w0); FMA2(A[1], ha.y, w0);
                FMA2(A[2], hb.x, w0); FMA2(A[3], hb.y, w0);
                FMA2(A[4], ha.x, w1); FMA2(A[5], ha.y, w1);
                FMA2(A[6], hb.x, w1); FMA2(A[7], hb.y, w1);

                if (LAYER == 2) {
                    float2 vv = *(const float2*)wi;  wi += 64;
                    unsigned long long v0, v1;
                    PACK2(v0, vv.x); PACK2(v1, vv.y);
                    ulonglong2 pa = *(const ulonglong2*)ppp;
                    ulonglong2 pb = *(const ulonglong2*)(ppp + 4);  ppp += 32;
                    FMA2(Bk[0], pa.x, v0); FMA2(Bk[1], pa.y, v0);
                    FMA2(Bk[2], pb.x, v0); FMA2(Bk[3], pb.y, v0);
                    FMA2(Bk[4], pa.x, v1); FMA2(Bk[5], pa.y, v1);
                    FMA2(Bk[6], pb.x, v1); FMA2(Bk[7], pb.y, v1);
                }
            }
        }
        // merge hh + ih accumulators
        float2 R[8];
        #pragma unroll
        for (int i = 0; i < 8; ++i) {
            float2 fa = u2f(A[i]);
            if (LAYER == 2) { float2 fb = u2f(Bk[i]); fa.x += fb.x; fa.y += fb.y; }
            R[i] = fa;
        }

        // ---- cross-kq reduction: kq 0->gsm, 2->part0, 3->part1; kq1 combines ----
        {
            float* dst = (kq == 0) ? gsm : (kq == 2) ? part0 : (kq == 3) ? part1 : (float*)0;
            if (dst) {
                #pragma unroll
                for (int p = 0; p < 4; ++p) {
                    int b = oct * 8 + 2 * p;
                    *(float2*)(dst + b * GSTR + 2 * rp)       = make_float2(R[p].x, R[4 + p].x);
                    *(float2*)(dst + (b + 1) * GSTR + 2 * rp) = make_float2(R[p].y, R[4 + p].y);
                }
            }
        }
        __syncthreads();   // sync1: h1_s reads done, kq0/kq2/kq3 partials written

        // ---- prefetch next step's inputs (h1_s dead until next loop top) ----
        if (LAYER == 2) {
            if (t + 1 < Tv) {
                const float* src = g_h1 + ((size_t)(t + 1) * Cv + c) * (Hv * Bv) + tid * 4;
                #pragma unroll
                for (int i = 0; i < 4; ++i) cp16(h1s_addr + i * 512u * 16u, src + i * 512 * 4);
                CP_COMMIT();
            }
        } else {
            if (tid < Bv && t + 1 < Tv)
                xr = __ldg(&x[(size_t)tid * Tv * Cv + (t + 1) * Cv + c]);
        }

        if (kq == 1) {
            #pragma unroll
            for (int p = 0; p < 4; ++p) {
                int b = oct * 8 + 2 * p;
                float2* g0 = (float2*)(gsm + b * GSTR + 2 * rp);
                float2* g1 = (float2*)(gsm + (b + 1) * GSTR + 2 * rp);
                float2 p00 = *(float2*)(part0 + b * GSTR + 2 * rp);
                float2 p01 = *(float2*)(part0 + (b + 1) * GSTR + 2 * rp);
                float2 p10 = *(float2*)(part1 + b * GSTR + 2 * rp);
                float2 p11 = *(float2*)(part1 + (b + 1) * GSTR + 2 * rp);
                float2 a = *g0, bb = *g1;
                a.x  += p00.x + p10.x + R[p].x;
                a.y  += p00.y + p10.y + R[4 + p].x;
                bb.x += p01.x + p11.x + R[p].y;
                bb.y += p01.y + p11.y + R[4 + p].y;
                *g0 = a; *g1 = bb;
            }
        }
        __syncthreads();   // sync2: gsm final (part0/part1 now dead until next sync1)

        // ---- activations + state update: thread -> (b = lane, j = warp) ----
        {
            const float* gr = gsm + ab * GSTR;
            float vi = gr[      aj] + bsum[      aj];
            float vf = gr[16 + aj] + bsum[16 + aj];
            float vg = gr[32 + aj] + bsum[32 + aj];
            float vo = gr[48 + aj] + bsum[48 + aj];
            if (LAYER == 1) {
                float xv = xs[ab];
                vi = fmaf(xv, wih1s[     aj], vi);
                vf = fmaf(xv, wih1s[16 + aj], vf);
                vg = fmaf(xv, wih1s[32 + aj], vg);
                vo = fmaf(xv, wih1s[48 + aj], vo);
            }
            float iv = sig_(vi), fv = sig_(vf), gv = tanh_(vg), ov = sig_(vo);
            float cn = fmaf(fv, c_s[tid], iv * gv);
            c_s[tid] = cn;
            float hn = ov * tanh_(cn);
            size_t hoff = ((size_t)c * Hv + jbase + aj) * Bv + ab;   // coalesced
            g_hbuf[(size_t)(t & 1) * (Cv * Hv * Bv) + hoff] = hn;
            if (LAYER == 1)
                g_h1[(((size_t)t * Cv + c) * Hv + jbase + aj) * Bv + ab] = hn;
            else
                part0[aj * 33 + ab] = hn * wlin16[aj];   // head partial staging (part0 dead here)
        }

        chan_barrier(c, lsense);

        // ---- reload full h[t] for this channel into h_s[k][b] ----
        {
            const float4* src = (const float4*)(g_hbuf + (size_t)(t & 1) * (Cv * Hv * Bv)
                                                        + (size_t)c * Hv * Bv);
            float4* dst = (float4*)h_s;
            #pragma unroll
            for (int i = 0; i < 4; ++i)
                dst[tid + i * 512] = __ldcg(src + tid + i * 512);
        }

        // ---- head partial: one warp sums this CTA's 16 j-lanes, stores off-path ----
        // part0 writes ordered by chan_barrier's syncthreads; next part0 write is
        // after the loop-top __syncthreads, so no race with this read.
        if (LAYER == 2 && tid < 32) {
            float s = 0.0f;
            #pragma unroll
            for (int j = 0; j < 16; ++j) s += part0[j * 33 + tid];
            g_opart[(((size_t)t * Cv + c) * 16 + rank) * Bv + tid] = s;
        }
        // loop-top __syncthreads orders h_s reload + part0 reads before next compute
    }
}

// ---------------- epilogue: out[b][t][c] = blin[c] + sum_rank opart[t][c][rank][b] ----------------
__global__ __launch_bounds__(256)
void head_kernel(const float* __restrict__ blin, float* __restrict__ out)
{
    int i  = blockIdx.x * 256 + threadIdx.x;   // 512 blocks x 256 = 131072 = B*T*C
    int b  = i & 31;
    int tc = i >> 5;                            // t*Cv + c
    int c  = tc & (Cv - 1);
    int t  = tc >> 3;
    const float* p = g_opart + (size_t)tc * 16 * Bv + b;
    float s = __ldg(&blin[c]);
    #pragma unroll
    for (int r = 0; r < 16; ++r) s += p[r * Bv];
    out[(size_t)b * Tv * Cv + t * Cv + c] = s;
}

// ---------------- launch ----------------
extern "C" void kernel_launch(void* const* d_in, const int* in_sizes, int n_in,
                              void* d_out, int out_size)
{
    const float* x    = (const float*)d_in[0];
    const float* Wih1 = (const float*)d_in[1];
    const float* Whh1 = (const float*)d_in[2];
    const float* bih1 = (const float*)d_in[3];
    const float* bhh1 = (const float*)d_in[4];
    const float* Wih2 = (const float*)d_in[5];
    const float* Whh2 = (const float*)d_in[6];
    const float* bih2 = (const float*)d_in[7];
    const float* bhh2 = (const float*)d_in[8];
    const float* Wlin = (const float*)d_in[9];
    const float* blin = (const float*)d_in[10];
    float* out = (float*)d_out;

    (void)in_sizes; (void)n_in; (void)out_size;

    cudaFuncSetAttribute(lstm_kernel<1>, cudaFuncAttributeMaxDynamicSharedMemorySize, SM_BYTES);
    cudaFuncSetAttribute(lstm_kernel<2>, cudaFuncAttributeMaxDynamicSharedMemorySize, SM_BYTES);

    lstm_kernel<1><<<128, 512, SM_BYTES>>>(x, Wih1, Whh1, bih1, bhh1, nullptr);
    lstm_kernel<2><<<128, 512, SM_BYTES>>>(nullptr, Wih2, Whh2, bih2, bhh2, Wlin);
    head_kernel<<<512, 256>>>(blin, out);
}